// round 16
// baseline (speedup 1.0000x reference)
#include <cuda_runtime.h>
#include <cuda_bf16.h>
#include <cuda_fp16.h>
#include <math.h>
#include <stdint.h>

#define ROWS   4096
#define DMODEL 1024
#define TSEQ   2048
#define DK     64
#define NGRP   32
#define OUT_ELEMS 4194304
#define ATTN_PER_G 4194304
#define GRP_STRIDE 131072

// Scratch
__device__ float g_q[ROWS * DMODEL];
__device__ float g_k[ROWS * DMODEL];
__device__ float g_v[ROWS * DMODEL];
__device__ __nv_bfloat16 g_xh[ROWS * DMODEL], g_xl[ROWS * DMODEL];
__device__ __nv_bfloat16 g_qh[ROWS * DMODEL], g_ql[ROWS * DMODEL];
__device__ __nv_bfloat16 g_kh[ROWS * DMODEL], g_kl[ROWS * DMODEL];
__device__ __nv_bfloat16 g_wh[3 * DMODEL * DMODEL], g_wl[3 * DMODEL * DMODEL];
__device__ __half g_vf[NGRP * DK * TSEQ];          // V^T fp16 [g][64][2048]
__device__ float2 g_pt[NGRP * 16 * TSEQ];          // softmax partials [g][tile][row]
__device__ unsigned short g_u[134217728];          // u = exp(alpha*s - m_tile), fp16

// ===========================================================================
__device__ __forceinline__ uint32_t smem_u32(const void* p) {
    uint32_t a;
    asm("{ .reg .u64 t; cvta.to.shared.u64 t, %1; cvt.u32.u64 %0, t; }"
        : "=r"(a) : "l"(p));
    return a;
}

__device__ __forceinline__ void ldsm4(uint32_t* r, uint32_t addr) {
    asm volatile("ldmatrix.sync.aligned.m8n8.x4.shared.b16 {%0,%1,%2,%3}, [%4];"
                 : "=r"(r[0]), "=r"(r[1]), "=r"(r[2]), "=r"(r[3]) : "r"(addr));
}

__device__ __forceinline__ void mma16816(float* c, const uint32_t* a,
                                         const uint32_t* b) {
    asm volatile(
        "mma.sync.aligned.m16n8k16.row.col.f32.bf16.bf16.f32 "
        "{%0,%1,%2,%3}, {%4,%5,%6,%7}, {%8,%9}, {%0,%1,%2,%3};"
        : "+f"(c[0]), "+f"(c[1]), "+f"(c[2]), "+f"(c[3])
        : "r"(a[0]), "r"(a[1]), "r"(a[2]), "r"(a[3]), "r"(b[0]), "r"(b[1]));
}

__device__ __forceinline__ void mma16816h(float* c, const uint32_t* a,
                                          const uint32_t* b) {
    asm volatile(
        "mma.sync.aligned.m16n8k16.row.col.f32.f16.f16.f32 "
        "{%0,%1,%2,%3}, {%4,%5,%6,%7}, {%8,%9}, {%0,%1,%2,%3};"
        : "+f"(c[0]), "+f"(c[1]), "+f"(c[2]), "+f"(c[3])
        : "r"(a[0]), "r"(a[1]), "r"(a[2]), "r"(a[3]), "r"(b[0]), "r"(b[1]));
}

__device__ __forceinline__ void cpa16(uint32_t dst, const void* src) {
    asm volatile("cp.async.cg.shared.global [%0], [%1], 16;"
                 :: "r"(dst), "l"(src));
}
#define CP_COMMIT() asm volatile("cp.async.commit_group;" ::: "memory")
#define CP_WAIT(n)  asm volatile("cp.async.wait_group %0;" :: "n"(n) : "memory")

__device__ __forceinline__ void split_f4(float4 v, uint2& hi, uint2& lo) {
    uint32_t u0 = __float_as_uint(v.x), u1 = __float_as_uint(v.y);
    uint32_t u2 = __float_as_uint(v.z), u3 = __float_as_uint(v.w);
    hi.x = (u0 >> 16) | (u1 & 0xFFFF0000u);
    hi.y = (u2 >> 16) | (u3 & 0xFFFF0000u);
    float l0 = v.x - __uint_as_float(u0 & 0xFFFF0000u);
    float l1 = v.y - __uint_as_float(u1 & 0xFFFF0000u);
    float l2 = v.z - __uint_as_float(u2 & 0xFFFF0000u);
    float l3 = v.w - __uint_as_float(u3 & 0xFFFF0000u);
    __nv_bfloat162 p01 = __floats2bfloat162_rn(l0, l1);
    __nv_bfloat162 p23 = __floats2bfloat162_rn(l2, l3);
    lo.x = *reinterpret_cast<uint32_t*>(&p01);
    lo.y = *reinterpret_cast<uint32_t*>(&p23);
}

__device__ __forceinline__ float norm_factor(float ssq_part, float scale) {
    float ssq = ssq_part;
    #pragma unroll
    for (int o = 16; o > 0; o >>= 1) ssq += __shfl_xor_sync(0xffffffffu, ssq, o);
    __shared__ float ws[8];
    int w = threadIdx.x >> 5, l = threadIdx.x & 31;
    if (l == 0) ws[w] = ssq;
    __syncthreads();
    if (w == 0) {
        float s = (l < 8) ? ws[l] : 0.0f;
        #pragma unroll
        for (int o = 4; o > 0; o >>= 1) s += __shfl_xor_sync(0xffffffffu, s, o);
        if (l == 0) ws[0] = s;
    }
    __syncthreads();
    return scale / fmaxf(sqrtf(ws[0]), 1e-5f);
}

// ===========================================================================
// prep: scalenorm_x rows + wsplit blocks in one launch
// ===========================================================================
__global__ __launch_bounds__(256) void prep_kernel(
    const float* __restrict__ in, const float* __restrict__ scale_p,
    __nv_bfloat16* __restrict__ oh, __nv_bfloat16* __restrict__ ol,
    const float* __restrict__ w0, const float* __restrict__ w1,
    const float* __restrict__ w2,
    __nv_bfloat16* __restrict__ wh, __nv_bfloat16* __restrict__ wl)
{
    int t = threadIdx.x;
    if (blockIdx.x < 4096) {
        int r = blockIdx.x;
        float4 f = ((const float4*)in)[(size_t)r * 256 + t];
        float fac = norm_factor(f.x*f.x + f.y*f.y + f.z*f.z + f.w*f.w, scale_p[0]);
        f.x *= fac; f.y *= fac; f.z *= fac; f.w *= fac;
        uint2 hi, lo;
        split_f4(f, hi, lo);
        size_t off = (size_t)r * 1024 + t * 4;
        *(uint2*)((char*)oh + off * 2) = hi;
        *(uint2*)((char*)ol + off * 2) = lo;
    } else {
        size_t idx = ((size_t)(blockIdx.x - 4096) * 256 + t) * 4;
        int which = (int)(idx >> 20);
        const float* src = (which == 0) ? w0 : (which == 1) ? w1 : w2;
        float4 f = *(const float4*)(src + (idx & 1048575));
        uint2 hi, lo;
        split_f4(f, hi, lo);
        *(uint2*)((char*)wh + idx * 2) = hi;
        *(uint2*)((char*)wl + idx * 2) = lo;
    }
}

// ===========================================================================
// scalenorm_qkv: z=0 q->slab hi/lo, z=1 k->slab hi/lo, z=2 v in place
// ===========================================================================
__global__ __launch_bounds__(256) void scalenorm_qkv(
    const float* __restrict__ q, const float* __restrict__ k,
    float* __restrict__ v, const float* __restrict__ scale_p,
    __nv_bfloat16* __restrict__ qh, __nv_bfloat16* __restrict__ ql,
    __nv_bfloat16* __restrict__ kh, __nv_bfloat16* __restrict__ kl)
{
    int z = blockIdx.y, r = blockIdx.x, t = threadIdx.x;
    const float* in = (z == 0) ? q : (z == 1) ? k : v;
    float4 f = ((const float4*)in)[(size_t)r * 256 + t];
    float fac = norm_factor(f.x*f.x + f.y*f.y + f.z*f.z + f.w*f.w, scale_p[0]);
    f.x *= fac; f.y *= fac; f.z *= fac; f.w *= fac;

    if (z == 2) { ((float4*)v)[(size_t)r * 256 + t] = f; return; }
    uint2 hi, lo;
    split_f4(f, hi, lo);
    size_t off = (size_t)r * 1024 + t * 4;
    if (z == 1) {
        *(uint2*)((char*)kh + off * 2) = hi;
        *(uint2*)((char*)kl + off * 2) = lo;
    } else {
        *(uint2*)((char*)qh + off * 2) = hi;
        *(uint2*)((char*)ql + off * 2) = lo;
    }
}

// ===========================================================================
// V^T fp16:  v[g][k=2048][n=64] fp32 -> vf[g][n=64][k=2048] fp16
// ===========================================================================
__global__ __launch_bounds__(256) void vt_convert(
    const float* __restrict__ v, __half* __restrict__ vf)
{
    int g  = blockIdx.z;
    int k0 = blockIdx.x * 64;
    const float* vg = v + (size_t)g * GRP_STRIDE;
    __shared__ float sm[64][68];
    int t = threadIdx.x;
    int kr = t >> 2, f4 = (t & 3) * 4;
    const float4* rp = (const float4*)(vg + (size_t)(k0 + kr) * DK);
    #pragma unroll
    for (int i = 0; i < 4; i++) {
        float4 f = rp[f4 + i];
        *(float4*)&sm[kr][(f4 + i) * 4] = f;
    }
    __syncthreads();
    int n = t >> 2;
    size_t ob = (size_t)g * (DK * TSEQ) + (size_t)n * TSEQ + k0;
    #pragma unroll
    for (int j = 0; j < 4; j++) {
        int kk = (t & 3) * 16 + j * 4;
        __half2 h01 = __floats2half2_rn(sm[kk+0][n], sm[kk+1][n]);
        __half2 h23 = __floats2half2_rn(sm[kk+2][n], sm[kk+3][n]);
        uint2 pk;
        pk.x = *reinterpret_cast<uint32_t*>(&h01);
        pk.y = *reinterpret_cast<uint32_t*>(&h23);
        *(uint2*)((char*)vf + (ob + kk) * 2) = pk;
    }
}

// ===========================================================================
// gemm_bb: BM=128, BN=128, BK=32, cp.async 3-stage.
// mode 0: proj (z: wq/wk/wv), fp32 C+bias epilogue.
// mode 1: QK (z=group): epilogue computes per-tile row max m_t,
//   writes u = fp16(exp(alpha*s - m_t)) and partial (m_t, sum) stats.
// ===========================================================================
#define NSTAGE  3
#define STG_SZ  32768
#define GB_SMEM (NSTAGE * STG_SZ)

__global__ __launch_bounds__(256, 2) void gemm_bb(
    int mode,
    const __nv_bfloat16* __restrict__ Ah, const __nv_bfloat16* __restrict__ Al,
    const __nv_bfloat16* __restrict__ Bh, const __nv_bfloat16* __restrict__ Bl,
    const float* __restrict__ bias0, const float* __restrict__ bias1,
    const float* __restrict__ bias2,
    float* __restrict__ C0, float* __restrict__ C1, float* __restrict__ C2,
    int lda, int ldb, int ldc, int K, float alpha,
    float2* __restrict__ ps, unsigned short* __restrict__ uout)
{
    extern __shared__ char smx[];
    uint32_t sbase = smem_u32(smx);

    const float* bias;
    float* C;
    int z = blockIdx.z;
    if (mode == 0) {
        Bh += (size_t)z * 1048576;  Bl += (size_t)z * 1048576;
        bias = (z == 0) ? bias0 : (z == 1) ? bias1 : bias2;
        C    = (z == 0) ? C0    : (z == 1) ? C1    : C2;
    } else {
        Ah += (size_t)z * 131072;   Al += (size_t)z * 131072;
        Bh += (size_t)z * 131072;   Bl += (size_t)z * 131072;
        bias = nullptr;
        C = nullptr;
        uout += (size_t)z * (size_t)ATTN_PER_G;
    }
    int rowBase = blockIdx.y * 128, colBase = blockIdx.x * 128;
    int tid = threadIdx.x, lane = tid & 31, wid = tid >> 5;
    int wm = wid >> 2, wn = wid & 3;

    int lr = tid >> 1, half = tid & 1;
    uint32_t swz = (lr >> 1) & 3;
    uint32_t d0 = lr * 64 + (((2u * half + 0) ^ swz) << 4);
    uint32_t d1 = lr * 64 + (((2u * half + 1) ^ swz) << 4);
    const char* aSrcH = (const char*)(Ah + (size_t)(rowBase + lr) * lda + half * 16);
    const char* aSrcL = (const char*)(Al + (size_t)(rowBase + lr) * lda + half * 16);
    const char* bSrcH = (const char*)(Bh + (size_t)(colBase + lr) * ldb + half * 16);
    const char* bSrcL = (const char*)(Bl + (size_t)(colBase + lr) * ldb + half * 16);

    int NC = K >> 5;

    auto issue = [&](int c, int s) {
        uint32_t st = sbase + s * STG_SZ;
        size_t ko = (size_t)c * 64;
        cpa16(st +         d0, aSrcH + ko);
        cpa16(st +         d1, aSrcH + ko + 16);
        cpa16(st +  8192 + d0, aSrcL + ko);
        cpa16(st +  8192 + d1, aSrcL + ko + 16);
        cpa16(st + 16384 + d0, bSrcH + ko);
        cpa16(st + 16384 + d1, bSrcH + ko + 16);
        cpa16(st + 24576 + d0, bSrcL + ko);
        cpa16(st + 24576 + d1, bSrcL + ko + 16);
        CP_COMMIT();
    };

    issue(0, 0);
    if (NC > 1) issue(1, 1);

    float acc[4][4][4];
    #pragma unroll
    for (int a = 0; a < 4; a++)
        #pragma unroll
        for (int b = 0; b < 4; b++)
            #pragma unroll
            for (int r = 0; r < 4; r++) acc[a][b][r] = 0.0f;

    int stage = 0;
    for (int c = 0; c < NC; c++) {
        if (c < NC - 1) CP_WAIT(1); else CP_WAIT(0);
        __syncthreads();
        if (c + NSTAGE - 1 < NC)
            issue(c + NSTAGE - 1, (stage + NSTAGE - 1) % NSTAGE);

        uint32_t stA = sbase + stage * STG_SZ;
        uint32_t stB = stA + 16384;
        #pragma unroll
        for (int kk = 0; kk < 2; kk++) {
            uint32_t ah[4][4], al[4][4];
            #pragma unroll
            for (int mt = 0; mt < 4; mt++) {
                int r = wm * 64 + mt * 16 + (lane & 15);
                uint32_t c16 = kk * 2 + (lane >> 4);
                uint32_t off = r * 64 + ((c16 ^ ((r >> 1) & 3)) << 4);
                ldsm4(ah[mt], stA + off);
                ldsm4(al[mt], stA + 8192 + off);
            }
            uint32_t bh[2][4], bl[2][4];
            #pragma unroll
            for (int np = 0; np < 2; np++) {
                int r = wn * 32 + np * 16 + ((lane >> 4) << 3) + (lane & 7);
                uint32_t c16 = kk * 2 + ((lane >> 3) & 1);
                uint32_t off = r * 64 + ((c16 ^ ((r >> 1) & 3)) << 4);
                ldsm4(bh[np], stB + off);
                ldsm4(bl[np], stB + 8192 + off);
            }
            #pragma unroll
            for (int mt = 0; mt < 4; mt++)
                #pragma unroll
                for (int nt = 0; nt < 4; nt++) {
                    const uint32_t* ph = &bh[nt >> 1][(nt & 1) * 2];
                    const uint32_t* pl = &bl[nt >> 1][(nt & 1) * 2];
                    mma16816(acc[mt][nt], ah[mt], ph);
                    mma16816(acc[mt][nt], ah[mt], pl);
                    mma16816(acc[mt][nt], al[mt], ph);
                }
        }
        __syncthreads();
        stage = (stage + 1) % NSTAGE;
    }

    if (mode == 0) {
        int r0 = rowBase + wm * 64 + (lane >> 2);
        int c0 = colBase + wn * 32 + (lane & 3) * 2;
        #pragma unroll
        for (int nt = 0; nt < 4; nt++) {
            int col = c0 + nt * 8;
            float b0 = bias[col], b1 = bias[col + 1];
            #pragma unroll
            for (int mt = 0; mt < 4; mt++) {
                int row = r0 + mt * 16;
                *(float2*)(C + (size_t)row * ldc + col) =
                    make_float2(acc[mt][nt][0] * alpha + b0,
                                acc[mt][nt][1] * alpha + b1);
                *(float2*)(C + (size_t)(row + 8) * ldc + col) =
                    make_float2(acc[mt][nt][2] * alpha + b0,
                                acc[mt][nt][3] * alpha + b1);
            }
        }
    } else {
        // QK epilogue: tile max -> u fp16 + partial stats
        float* pm = (float*)smx;
        float* pu = (float*)(smx + 2048);
        #pragma unroll
        for (int mt = 0; mt < 4; mt++)
            #pragma unroll
            for (int hf = 0; hf < 2; hf++) {
                float m = -3.4e38f;
                #pragma unroll
                for (int nt = 0; nt < 4; nt++)
                    m = fmaxf(m, fmaxf(acc[mt][nt][hf*2], acc[mt][nt][hf*2+1]));
                m *= alpha;
                m = fmaxf(m, __shfl_xor_sync(0xffffffffu, m, 1));
                m = fmaxf(m, __shfl_xor_sync(0xffffffffu, m, 2));
                if ((lane & 3) == 0) {
                    int lrow = wm * 64 + mt * 16 + hf * 8 + (lane >> 2);
                    pm[wn * 128 + lrow] = m;
                }
            }
        __syncthreads();
        #pragma unroll
        for (int mt = 0; mt < 4; mt++)
            #pragma unroll
            for (int hf = 0; hf < 2; hf++) {
                int lrow = wm * 64 + mt * 16 + hf * 8 + (lane >> 2);
                float m_t = fmaxf(fmaxf(pm[lrow], pm[128 + lrow]),
                                  fmaxf(pm[256 + lrow], pm[384 + lrow]));
                int row = rowBase + lrow;
                float tsum = 0.0f;
                #pragma unroll
                for (int nt = 0; nt < 4; nt++) {
                    float e0 = __expf(acc[mt][nt][hf*2]   * alpha - m_t);
                    float e1 = __expf(acc[mt][nt][hf*2+1] * alpha - m_t);
                    tsum += e0 + e1;
                    int col = colBase + wn * 32 + nt * 8 + (lane & 3) * 2;
                    __half2 h2 = __floats2half2_rn(e0, e1);
                    *(uint32_t*)((char*)uout + ((size_t)row * TSEQ + col) * 2) =
                        *reinterpret_cast<uint32_t*>(&h2);
                }
                tsum += __shfl_xor_sync(0xffffffffu, tsum, 1);
                tsum += __shfl_xor_sync(0xffffffffu, tsum, 2);
                if ((lane & 3) == 0) pu[wn * 128 + lrow] = tsum;
            }
        __syncthreads();
        if (tid < 128) {
            float m = fmaxf(fmaxf(pm[tid], pm[128 + tid]),
                            fmaxf(pm[256 + tid], pm[384 + tid]));
            float s = pu[tid] + pu[128 + tid] + pu[256 + tid] + pu[384 + tid];
            ps[((size_t)z * 16 + blockIdx.x) * TSEQ + rowBase + tid] =
                make_float2(m, s);
        }
    }
}

// ===========================================================================
// pv_fuse: fp16 direct MMA, 5-stage pipeline (prefetch distance 4).
// smem: U 5x8K | vf 5x4K | ef 8K = 68K (2 CTAs/SM)
// ===========================================================================
#define PV_NST      5
#define PVF_S_OFF   0
#define PVF_V_OFF   40960
#define PVF_EF_OFF  61440
#define PVF_SMEM    69632

__global__ __launch_bounds__(256, 2) void pv_fuse(
    const unsigned short* __restrict__ U, const float2* __restrict__ pt,
    const __half* __restrict__ vf,
    float* __restrict__ attn, float* __restrict__ Out)
{
    extern __shared__ char smx[];
    uint32_t sbase = smem_u32(smx);
    float* efb = (float*)(smx + PVF_EF_OFF);

    int g = blockIdx.z;
    int rowBase = blockIdx.x * 128;
    const char* uG  = (const char*)(U + (size_t)g * ATTN_PER_G);
    const char* vfG = (const char*)(vf + (size_t)g * (DK * TSEQ));
    float* Sg = attn + (size_t)g * ATTN_PER_G;

    int tid = threadIdx.x, lane = tid & 31, wid = tid >> 5;
    int wm = wid >> 1, wn = wid & 1;

    auto issue = [&](int c, int s) {
        uint32_t stS = sbase + PVF_S_OFF + s * 8192;
        #pragma unroll
        for (int t4 = 0; t4 < 2; t4++) {
            int id = tid + t4 * 256;
            int r = id >> 2, c16 = id & 3;
            uint32_t dst = stS + r * 64 + (((uint32_t)c16 ^ ((r >> 1) & 3)) << 4);
            cpa16(dst, uG + (size_t)(rowBase + r) * 4096 + (size_t)c * 64 + c16 * 16);
        }
        {
            uint32_t stV = sbase + PVF_V_OFF + s * 4096;
            int r = tid >> 2, c16 = tid & 3;
            uint32_t dst = stV + r * 64 + (((uint32_t)c16 ^ ((r >> 1) & 3)) << 4);
            cpa16(dst, vfG + (size_t)r * 4096 + (size_t)c * 64 + c16 * 16);
        }
        CP_COMMIT();
    };

    issue(0, 0);
    issue(1, 1);
    issue(2, 2);
    issue(3, 3);

    if (tid < 128) {
        const float2* pp = pt + (size_t)g * 16 * TSEQ + rowBase + tid;
        float m = -3.4e38f, s = 0.0f;
        #pragma unroll
        for (int t = 0; t < 16; t++) {
            float2 q = pp[(size_t)t * TSEQ];
            efb[t * 128 + tid] = q.x;
            float mn = fmaxf(m, q.x);
            s = s * __expf(m - mn) + q.y * __expf(q.x - mn);
            m = mn;
        }
        float inv = 1.0f / s;
        #pragma unroll
        for (int t = 0; t < 16; t++)
            efb[t * 128 + tid] = __expf(efb[t * 128 + tid] - m) * inv;
    }
    __syncthreads();

    float oacc[2][4][4], tacc[2][4][4];
    #pragma unroll
    for (int a = 0; a < 2; a++)
        #pragma unroll
        for (int b = 0; b < 4; b++)
            #pragma unroll
            for (int r = 0; r < 4; r++) oacc[a][b][r] = 0.0f;

    const int NC = TSEQ >> 5;   // 64
    int stage = 0;
    for (int c = 0; c < NC; c++) {
        if (c < NC - 4) CP_WAIT(3); else CP_WAIT(0);
        __syncthreads();
        if (c + 4 < NC) issue(c + 4, (stage + 4) % PV_NST);

        int tidx = c >> 2;
        uint32_t stS = sbase + PVF_S_OFF + stage * 8192;
        uint32_t stV = sbase + PVF_V_OFF + stage * 4096;

        // P write: p = fp16(u) * ef
        #pragma unroll
        for (int it = 0; it < 4; it++) {
            int r  = (tid >> 3) + it * 32;
            int c4 = tid & 7;
            uint32_t c16 = (uint32_t)(c4 >> 1);
            uint32_t sub = (c4 & 1) * 8;
            uint2 up = *(uint2*)(smx + PVF_S_OFF + stage * 8192
                                 + r * 64 + ((c16 ^ ((r >> 1) & 3)) << 4) + sub);
            __half2 h01 = *reinterpret_cast<__half2*>(&up.x);
            __half2 h23 = *reinterpret_cast<__half2*>(&up.y);
            float2 f01 = __half22float2(h01);
            float2 f23 = __half22float2(h23);
            float ef = efb[tidx * 128 + r];
            float4 p;
            p.x = f01.x * ef; p.y = f01.y * ef;
            p.z = f23.x * ef; p.w = f23.y * ef;
            *(float4*)(Sg + (size_t)(rowBase + r) * TSEQ + c * 32 + c4 * 4) = p;
        }

        if ((c & 3) == 0) {
            #pragma unroll
            for (int a = 0; a < 2; a++)
                #pragma unroll
                for (int b = 0; b < 4; b++)
                    #pragma unroll
                    for (int r = 0; r < 4; r++) tacc[a][b][r] = 0.0f;
        }

        // MMA: tacc += U @ V (fp16 direct)
        #pragma unroll
        for (int kk = 0; kk < 2; kk++) {
            uint32_t au[2][4];
            #pragma unroll
            for (int mt = 0; mt < 2; mt++) {
                int r = wm * 32 + mt * 16 + (lane & 15);
                uint32_t c16 = kk * 2 + (lane >> 4);
                uint32_t off = r * 64 + ((c16 ^ ((r >> 1) & 3)) << 4);
                ldsm4(au[mt], stS + off);
            }
            uint32_t bv[2][4];
            #pragma unroll
            for (int np = 0; np < 2; np++) {
                int n = wn * 32 + np * 16 + ((lane >> 4) << 3) + (lane & 7);
                uint32_t c16 = kk * 2 + ((lane >> 3) & 1);
                uint32_t off = n * 64 + ((c16 ^ ((n >> 1) & 3)) << 4);
                ldsm4(bv[np], stV + off);
            }
            #pragma unroll
            for (int mt = 0; mt < 2; mt++)
                #pragma unroll
                for (int nt = 0; nt < 4; nt++)
                    mma16816h(tacc[mt][nt], au[mt], &bv[nt >> 1][(nt & 1) * 2]);
        }

        // fold at tile end: O += ef[row] * tacc
        if ((c & 3) == 3) {
            #pragma unroll
            for (int mt = 0; mt < 2; mt++)
                #pragma unroll
                for (int hf = 0; hf < 2; hf++) {
                    int row = wm * 32 + mt * 16 + hf * 8 + (lane >> 2);
                    float ef = efb[tidx * 128 + row];
                    #pragma unroll
                    for (int nt = 0; nt < 4; nt++) {
                        oacc[mt][nt][hf*2]   += ef * tacc[mt][nt][hf*2];
                        oacc[mt][nt][hf*2+1] += ef * tacc[mt][nt][hf*2+1];
                    }
                }
        }
        stage = (stage + 1) % PV_NST;
    }

    // scatter epilogue (validated)
    int b  = g >> 4;
    int gg = g & 15;
    float* ob = Out + (size_t)b * 2097152;
    int rr  = rowBase + wm * 32 + (lane >> 2);
    int en0 = wn * 32 + (lane & 3) * 2;
    #pragma unroll
    for (int mt = 0; mt < 2; mt++) {
        #pragma unroll
        for (int hf = 0; hf < 2; hf++) {
            int s   = rr + mt * 16 + hf * 8;
            int thi = s >> 10;
            int d   = s & 1023;
            #pragma unroll
            for (int nt = 0; nt < 4; nt++) {
                int e  = en0 + nt * 8;
                int t0 = gg * 128 + 2 * e + thi;
                int t1 = gg * 128 + 2 * (e + 1) + thi;
                ob[(size_t)t0 * 1024 + d] = oacc[mt][nt][hf * 2 + 0];
                ob[(size_t)t1 * 1024 + d] = oacc[mt][nt][hf * 2 + 1];
            }
        }
    }
}

// ===========================================================================
// kernel_launch
// ===========================================================================
extern "C" void kernel_launch(void* const* d_in, const int* in_sizes, int n_in,
                              void* d_out, int out_size)
{
    const float* x  = (const float*)d_in[0];
    const float* sc = (const float*)d_in[1];
    const float* wq = (const float*)d_in[2];
    const float* bq = (const float*)d_in[3];
    const float* wk = (const float*)d_in[4];
    const float* bk = (const float*)d_in[5];
    const float* wv = (const float*)d_in[6];
    const float* bv = (const float*)d_in[7];

    float* out  = (float*)d_out;
    float* attn = out + OUT_ELEMS;

    float *q, *k, *v;
    float2* pt;
    unsigned short* u;
    __half* vf;
    __nv_bfloat16 *xh, *xl, *qh, *ql, *kh, *kl, *wh, *wl;
    cudaGetSymbolAddress((void**)&q,  g_q);
    cudaGetSymbolAddress((void**)&k,  g_k);
    cudaGetSymbolAddress((void**)&v,  g_v);
    cudaGetSymbolAddress((void**)&xh, g_xh);
    cudaGetSymbolAddress((void**)&xl, g_xl);
    cudaGetSymbolAddress((void**)&qh, g_qh);
    cudaGetSymbolAddress((void**)&ql, g_ql);
    cudaGetSymbolAddress((void**)&kh, g_kh);
    cudaGetSymbolAddress((void**)&kl, g_kl);
    cudaGetSymbolAddress((void**)&wh, g_wh);
    cudaGetSymbolAddress((void**)&wl, g_wl);
    cudaGetSymbolAddress((void**)&vf, g_vf);
    cudaGetSymbolAddress((void**)&pt, g_pt);
    cudaGetSymbolAddress((void**)&u,  g_u);

    cudaFuncSetAttribute(gemm_bb, cudaFuncAttributeMaxDynamicSharedMemorySize, GB_SMEM);
    cudaFuncSetAttribute(pv_fuse, cudaFuncAttributeMaxDynamicSharedMemorySize, PVF_SMEM);

    // 1) normalize x + split weights (fused launch)
    prep_kernel<<<4096 + 3072, 256>>>(x, sc, xh, xl, wq, wk, wv, wh, wl);

    // 2) projections (batched)
    gemm_bb<<<dim3(8, 32, 3), 256, GB_SMEM>>>(
        0, xh, xl, wh, wl, bq, bk, bv, q, k, v,
        DMODEL, DMODEL, DMODEL, DMODEL, 1.0f, nullptr, nullptr);

    // 3) scale_norm q/k/v
    scalenorm_qkv<<<dim3(ROWS, 3), 256>>>(q, k, v, sc, qh, ql, kh, kl);

    // 3b) V^T fp16
    vt_convert<<<dim3(TSEQ / 64, 1, NGRP), 256>>>(v, vf);

    // 4) QK: u = fp16 exp-domain S + per-tile softmax partials
    gemm_bb<<<dim3(16, 16, NGRP), 256, GB_SMEM>>>(
        1, qh, ql, kh, kl, nullptr, nullptr, nullptr, nullptr, nullptr, nullptr,
        DK, DK, TSEQ, DK, 0.125f, pt, u);

    // 5+6) fused softmax + P write + O = P @ V (fp16 direct MMA, 5-stage)
    pv_fuse<<<dim3(TSEQ / 128, 1, NGRP), 256, PVF_SMEM>>>(u, pt, vf, attn, out);
}

// round 17
// speedup vs baseline: 1.0777x; 1.0777x over previous
#include <cuda_runtime.h>
#include <cuda_bf16.h>
#include <cuda_fp16.h>
#include <math.h>
#include <stdint.h>

#define ROWS   4096
#define DMODEL 1024
#define TSEQ   2048
#define DK     64
#define NGRP   32
#define OUT_ELEMS 4194304
#define ATTN_PER_G 4194304
#define GRP_STRIDE 131072

// Scratch
__device__ float g_q[ROWS * DMODEL];
__device__ float g_k[ROWS * DMODEL];
__device__ float g_v[ROWS * DMODEL];
__device__ __nv_bfloat16 g_xh[ROWS * DMODEL], g_xl[ROWS * DMODEL];
__device__ __nv_bfloat16 g_qh[ROWS * DMODEL], g_ql[ROWS * DMODEL];
__device__ __nv_bfloat16 g_kh[ROWS * DMODEL], g_kl[ROWS * DMODEL];
__device__ __nv_bfloat16 g_wh[3 * DMODEL * DMODEL], g_wl[3 * DMODEL * DMODEL];
__device__ __half g_vf[NGRP * DK * TSEQ];          // V^T fp16 [g][64][2048]
__device__ float2 g_pt[NGRP * 16 * TSEQ];          // softmax partials [g][tile][row]
__device__ unsigned short g_u[134217728];          // u = exp(alpha*s - m_tile), fp16

// ===========================================================================
__device__ __forceinline__ uint32_t smem_u32(const void* p) {
    uint32_t a;
    asm("{ .reg .u64 t; cvta.to.shared.u64 t, %1; cvt.u32.u64 %0, t; }"
        : "=r"(a) : "l"(p));
    return a;
}

__device__ __forceinline__ void ldsm4(uint32_t* r, uint32_t addr) {
    asm volatile("ldmatrix.sync.aligned.m8n8.x4.shared.b16 {%0,%1,%2,%3}, [%4];"
                 : "=r"(r[0]), "=r"(r[1]), "=r"(r[2]), "=r"(r[3]) : "r"(addr));
}

__device__ __forceinline__ void mma16816(float* c, const uint32_t* a,
                                         const uint32_t* b) {
    asm volatile(
        "mma.sync.aligned.m16n8k16.row.col.f32.bf16.bf16.f32 "
        "{%0,%1,%2,%3}, {%4,%5,%6,%7}, {%8,%9}, {%0,%1,%2,%3};"
        : "+f"(c[0]), "+f"(c[1]), "+f"(c[2]), "+f"(c[3])
        : "r"(a[0]), "r"(a[1]), "r"(a[2]), "r"(a[3]), "r"(b[0]), "r"(b[1]));
}

__device__ __forceinline__ void mma16816h(float* c, const uint32_t* a,
                                          const uint32_t* b) {
    asm volatile(
        "mma.sync.aligned.m16n8k16.row.col.f32.f16.f16.f32 "
        "{%0,%1,%2,%3}, {%4,%5,%6,%7}, {%8,%9}, {%0,%1,%2,%3};"
        : "+f"(c[0]), "+f"(c[1]), "+f"(c[2]), "+f"(c[3])
        : "r"(a[0]), "r"(a[1]), "r"(a[2]), "r"(a[3]), "r"(b[0]), "r"(b[1]));
}

__device__ __forceinline__ void cpa16(uint32_t dst, const void* src) {
    asm volatile("cp.async.cg.shared.global [%0], [%1], 16;"
                 :: "r"(dst), "l"(src));
}
#define CP_COMMIT() asm volatile("cp.async.commit_group;" ::: "memory")
#define CP_WAIT(n)  asm volatile("cp.async.wait_group %0;" :: "n"(n) : "memory")

__device__ __forceinline__ void split_f4(float4 v, uint2& hi, uint2& lo) {
    uint32_t u0 = __float_as_uint(v.x), u1 = __float_as_uint(v.y);
    uint32_t u2 = __float_as_uint(v.z), u3 = __float_as_uint(v.w);
    hi.x = (u0 >> 16) | (u1 & 0xFFFF0000u);
    hi.y = (u2 >> 16) | (u3 & 0xFFFF0000u);
    float l0 = v.x - __uint_as_float(u0 & 0xFFFF0000u);
    float l1 = v.y - __uint_as_float(u1 & 0xFFFF0000u);
    float l2 = v.z - __uint_as_float(u2 & 0xFFFF0000u);
    float l3 = v.w - __uint_as_float(u3 & 0xFFFF0000u);
    __nv_bfloat162 p01 = __floats2bfloat162_rn(l0, l1);
    __nv_bfloat162 p23 = __floats2bfloat162_rn(l2, l3);
    lo.x = *reinterpret_cast<uint32_t*>(&p01);
    lo.y = *reinterpret_cast<uint32_t*>(&p23);
}

__device__ __forceinline__ float norm_factor(float ssq_part, float scale) {
    float ssq = ssq_part;
    #pragma unroll
    for (int o = 16; o > 0; o >>= 1) ssq += __shfl_xor_sync(0xffffffffu, ssq, o);
    __shared__ float ws[8];
    int w = threadIdx.x >> 5, l = threadIdx.x & 31;
    if (l == 0) ws[w] = ssq;
    __syncthreads();
    if (w == 0) {
        float s = (l < 8) ? ws[l] : 0.0f;
        #pragma unroll
        for (int o = 4; o > 0; o >>= 1) s += __shfl_xor_sync(0xffffffffu, s, o);
        if (l == 0) ws[0] = s;
    }
    __syncthreads();
    return scale / fmaxf(sqrtf(ws[0]), 1e-5f);
}

// ===========================================================================
// prep: scalenorm_x rows + wsplit blocks in one launch
// ===========================================================================
__global__ __launch_bounds__(256) void prep_kernel(
    const float* __restrict__ in, const float* __restrict__ scale_p,
    __nv_bfloat16* __restrict__ oh, __nv_bfloat16* __restrict__ ol,
    const float* __restrict__ w0, const float* __restrict__ w1,
    const float* __restrict__ w2,
    __nv_bfloat16* __restrict__ wh, __nv_bfloat16* __restrict__ wl)
{
    int t = threadIdx.x;
    if (blockIdx.x < 4096) {
        int r = blockIdx.x;
        float4 f = ((const float4*)in)[(size_t)r * 256 + t];
        float fac = norm_factor(f.x*f.x + f.y*f.y + f.z*f.z + f.w*f.w, scale_p[0]);
        f.x *= fac; f.y *= fac; f.z *= fac; f.w *= fac;
        uint2 hi, lo;
        split_f4(f, hi, lo);
        size_t off = (size_t)r * 1024 + t * 4;
        *(uint2*)((char*)oh + off * 2) = hi;
        *(uint2*)((char*)ol + off * 2) = lo;
    } else {
        size_t idx = ((size_t)(blockIdx.x - 4096) * 256 + t) * 4;
        int which = (int)(idx >> 20);
        const float* src = (which == 0) ? w0 : (which == 1) ? w1 : w2;
        float4 f = *(const float4*)(src + (idx & 1048575));
        uint2 hi, lo;
        split_f4(f, hi, lo);
        *(uint2*)((char*)wh + idx * 2) = hi;
        *(uint2*)((char*)wl + idx * 2) = lo;
    }
}

// ===========================================================================
// scalenorm_qkv: z=0 q->slab hi/lo, z=1 k->slab hi/lo, z=2 v in place
// ===========================================================================
__global__ __launch_bounds__(256) void scalenorm_qkv(
    const float* __restrict__ q, const float* __restrict__ k,
    float* __restrict__ v, const float* __restrict__ scale_p,
    __nv_bfloat16* __restrict__ qh, __nv_bfloat16* __restrict__ ql,
    __nv_bfloat16* __restrict__ kh, __nv_bfloat16* __restrict__ kl)
{
    int z = blockIdx.y, r = blockIdx.x, t = threadIdx.x;
    const float* in = (z == 0) ? q : (z == 1) ? k : v;
    float4 f = ((const float4*)in)[(size_t)r * 256 + t];
    float fac = norm_factor(f.x*f.x + f.y*f.y + f.z*f.z + f.w*f.w, scale_p[0]);
    f.x *= fac; f.y *= fac; f.z *= fac; f.w *= fac;

    if (z == 2) { ((float4*)v)[(size_t)r * 256 + t] = f; return; }
    uint2 hi, lo;
    split_f4(f, hi, lo);
    size_t off = (size_t)r * 1024 + t * 4;
    if (z == 1) {
        *(uint2*)((char*)kh + off * 2) = hi;
        *(uint2*)((char*)kl + off * 2) = lo;
    } else {
        *(uint2*)((char*)qh + off * 2) = hi;
        *(uint2*)((char*)ql + off * 2) = lo;
    }
}

// ===========================================================================
// V^T fp16:  v[g][k=2048][n=64] fp32 -> vf[g][n=64][k=2048] fp16
// ===========================================================================
__global__ __launch_bounds__(256) void vt_convert(
    const float* __restrict__ v, __half* __restrict__ vf)
{
    int g  = blockIdx.z;
    int k0 = blockIdx.x * 64;
    const float* vg = v + (size_t)g * GRP_STRIDE;
    __shared__ float sm[64][68];
    int t = threadIdx.x;
    int kr = t >> 2, f4 = (t & 3) * 4;
    const float4* rp = (const float4*)(vg + (size_t)(k0 + kr) * DK);
    #pragma unroll
    for (int i = 0; i < 4; i++) {
        float4 f = rp[f4 + i];
        *(float4*)&sm[kr][(f4 + i) * 4] = f;
    }
    __syncthreads();
    int n = t >> 2;
    size_t ob = (size_t)g * (DK * TSEQ) + (size_t)n * TSEQ + k0;
    #pragma unroll
    for (int j = 0; j < 4; j++) {
        int kk = (t & 3) * 16 + j * 4;
        __half2 h01 = __floats2half2_rn(sm[kk+0][n], sm[kk+1][n]);
        __half2 h23 = __floats2half2_rn(sm[kk+2][n], sm[kk+3][n]);
        uint2 pk;
        pk.x = *reinterpret_cast<uint32_t*>(&h01);
        pk.y = *reinterpret_cast<uint32_t*>(&h23);
        *(uint2*)((char*)vf + (ob + kk) * 2) = pk;
    }
}

// ===========================================================================
// gemm_bb: BM=128, BN=128, BK=32, cp.async 3-stage.  (R14 exact)
// ===========================================================================
#define NSTAGE  3
#define STG_SZ  32768
#define GB_SMEM (NSTAGE * STG_SZ)

__global__ __launch_bounds__(256, 2) void gemm_bb(
    int mode,
    const __nv_bfloat16* __restrict__ Ah, const __nv_bfloat16* __restrict__ Al,
    const __nv_bfloat16* __restrict__ Bh, const __nv_bfloat16* __restrict__ Bl,
    const float* __restrict__ bias0, const float* __restrict__ bias1,
    const float* __restrict__ bias2,
    float* __restrict__ C0, float* __restrict__ C1, float* __restrict__ C2,
    int lda, int ldb, int ldc, int K, float alpha,
    float2* __restrict__ ps, unsigned short* __restrict__ uout)
{
    extern __shared__ char smx[];
    uint32_t sbase = smem_u32(smx);

    const float* bias;
    float* C;
    int z = blockIdx.z;
    if (mode == 0) {
        Bh += (size_t)z * 1048576;  Bl += (size_t)z * 1048576;
        bias = (z == 0) ? bias0 : (z == 1) ? bias1 : bias2;
        C    = (z == 0) ? C0    : (z == 1) ? C1    : C2;
    } else {
        Ah += (size_t)z * 131072;   Al += (size_t)z * 131072;
        Bh += (size_t)z * 131072;   Bl += (size_t)z * 131072;
        bias = nullptr;
        C = nullptr;
        uout += (size_t)z * (size_t)ATTN_PER_G;
    }
    int rowBase = blockIdx.y * 128, colBase = blockIdx.x * 128;
    int tid = threadIdx.x, lane = tid & 31, wid = tid >> 5;
    int wm = wid >> 2, wn = wid & 3;

    int lr = tid >> 1, half = tid & 1;
    uint32_t swz = (lr >> 1) & 3;
    uint32_t d0 = lr * 64 + (((2u * half + 0) ^ swz) << 4);
    uint32_t d1 = lr * 64 + (((2u * half + 1) ^ swz) << 4);
    const char* aSrcH = (const char*)(Ah + (size_t)(rowBase + lr) * lda + half * 16);
    const char* aSrcL = (const char*)(Al + (size_t)(rowBase + lr) * lda + half * 16);
    const char* bSrcH = (const char*)(Bh + (size_t)(colBase + lr) * ldb + half * 16);
    const char* bSrcL = (const char*)(Bl + (size_t)(colBase + lr) * ldb + half * 16);

    int NC = K >> 5;

    auto issue = [&](int c, int s) {
        uint32_t st = sbase + s * STG_SZ;
        size_t ko = (size_t)c * 64;
        cpa16(st +         d0, aSrcH + ko);
        cpa16(st +         d1, aSrcH + ko + 16);
        cpa16(st +  8192 + d0, aSrcL + ko);
        cpa16(st +  8192 + d1, aSrcL + ko + 16);
        cpa16(st + 16384 + d0, bSrcH + ko);
        cpa16(st + 16384 + d1, bSrcH + ko + 16);
        cpa16(st + 24576 + d0, bSrcL + ko);
        cpa16(st + 24576 + d1, bSrcL + ko + 16);
        CP_COMMIT();
    };

    issue(0, 0);
    if (NC > 1) issue(1, 1);

    float acc[4][4][4];
    #pragma unroll
    for (int a = 0; a < 4; a++)
        #pragma unroll
        for (int b = 0; b < 4; b++)
            #pragma unroll
            for (int r = 0; r < 4; r++) acc[a][b][r] = 0.0f;

    int stage = 0;
    for (int c = 0; c < NC; c++) {
        if (c < NC - 1) CP_WAIT(1); else CP_WAIT(0);
        __syncthreads();
        if (c + NSTAGE - 1 < NC)
            issue(c + NSTAGE - 1, (stage + NSTAGE - 1) % NSTAGE);

        uint32_t stA = sbase + stage * STG_SZ;
        uint32_t stB = stA + 16384;
        #pragma unroll
        for (int kk = 0; kk < 2; kk++) {
            uint32_t ah[4][4], al[4][4];
            #pragma unroll
            for (int mt = 0; mt < 4; mt++) {
                int r = wm * 64 + mt * 16 + (lane & 15);
                uint32_t c16 = kk * 2 + (lane >> 4);
                uint32_t off = r * 64 + ((c16 ^ ((r >> 1) & 3)) << 4);
                ldsm4(ah[mt], stA + off);
                ldsm4(al[mt], stA + 8192 + off);
            }
            uint32_t bh[2][4], bl[2][4];
            #pragma unroll
            for (int np = 0; np < 2; np++) {
                int r = wn * 32 + np * 16 + ((lane >> 4) << 3) + (lane & 7);
                uint32_t c16 = kk * 2 + ((lane >> 3) & 1);
                uint32_t off = r * 64 + ((c16 ^ ((r >> 1) & 3)) << 4);
                ldsm4(bh[np], stB + off);
                ldsm4(bl[np], stB + 8192 + off);
            }
            #pragma unroll
            for (int mt = 0; mt < 4; mt++)
                #pragma unroll
                for (int nt = 0; nt < 4; nt++) {
                    const uint32_t* ph = &bh[nt >> 1][(nt & 1) * 2];
                    const uint32_t* pl = &bl[nt >> 1][(nt & 1) * 2];
                    mma16816(acc[mt][nt], ah[mt], ph);
                    mma16816(acc[mt][nt], ah[mt], pl);
                    mma16816(acc[mt][nt], al[mt], ph);
                }
        }
        __syncthreads();
        stage = (stage + 1) % NSTAGE;
    }

    if (mode == 0) {
        int r0 = rowBase + wm * 64 + (lane >> 2);
        int c0 = colBase + wn * 32 + (lane & 3) * 2;
        #pragma unroll
        for (int nt = 0; nt < 4; nt++) {
            int col = c0 + nt * 8;
            float b0 = bias[col], b1 = bias[col + 1];
            #pragma unroll
            for (int mt = 0; mt < 4; mt++) {
                int row = r0 + mt * 16;
                *(float2*)(C + (size_t)row * ldc + col) =
                    make_float2(acc[mt][nt][0] * alpha + b0,
                                acc[mt][nt][1] * alpha + b1);
                *(float2*)(C + (size_t)(row + 8) * ldc + col) =
                    make_float2(acc[mt][nt][2] * alpha + b0,
                                acc[mt][nt][3] * alpha + b1);
            }
        }
    } else {
        // QK epilogue: tile max -> u fp16 + partial stats
        float* pm = (float*)smx;
        float* pu = (float*)(smx + 2048);
        #pragma unroll
        for (int mt = 0; mt < 4; mt++)
            #pragma unroll
            for (int hf = 0; hf < 2; hf++) {
                float m = -3.4e38f;
                #pragma unroll
                for (int nt = 0; nt < 4; nt++)
                    m = fmaxf(m, fmaxf(acc[mt][nt][hf*2], acc[mt][nt][hf*2+1]));
                m *= alpha;
                m = fmaxf(m, __shfl_xor_sync(0xffffffffu, m, 1));
                m = fmaxf(m, __shfl_xor_sync(0xffffffffu, m, 2));
                if ((lane & 3) == 0) {
                    int lrow = wm * 64 + mt * 16 + hf * 8 + (lane >> 2);
                    pm[wn * 128 + lrow] = m;
                }
            }
        __syncthreads();
        #pragma unroll
        for (int mt = 0; mt < 4; mt++)
            #pragma unroll
            for (int hf = 0; hf < 2; hf++) {
                int lrow = wm * 64 + mt * 16 + hf * 8 + (lane >> 2);
                float m_t = fmaxf(fmaxf(pm[lrow], pm[128 + lrow]),
                                  fmaxf(pm[256 + lrow], pm[384 + lrow]));
                int row = rowBase + lrow;
                float tsum = 0.0f;
                #pragma unroll
                for (int nt = 0; nt < 4; nt++) {
                    float e0 = __expf(acc[mt][nt][hf*2]   * alpha - m_t);
                    float e1 = __expf(acc[mt][nt][hf*2+1] * alpha - m_t);
                    tsum += e0 + e1;
                    int col = colBase + wn * 32 + nt * 8 + (lane & 3) * 2;
                    __half2 h2 = __floats2half2_rn(e0, e1);
                    *(uint32_t*)((char*)uout + ((size_t)row * TSEQ + col) * 2) =
                        *reinterpret_cast<uint32_t*>(&h2);
                }
                tsum += __shfl_xor_sync(0xffffffffu, tsum, 1);
                tsum += __shfl_xor_sync(0xffffffffu, tsum, 2);
                if ((lane & 3) == 0) pu[wn * 128 + lrow] = tsum;
            }
        __syncthreads();
        if (tid < 128) {
            float m = fmaxf(fmaxf(pm[tid], pm[128 + tid]),
                            fmaxf(pm[256 + tid], pm[384 + tid]));
            float s = pu[tid] + pu[128 + tid] + pu[256 + tid] + pu[384 + tid];
            ps[((size_t)z * 16 + blockIdx.x) * TSEQ + rowBase + tid] =
                make_float2(m, s);
        }
    }
}

// ===========================================================================
// pv_fuse: fp16 direct MMA, 64-col chunks (32 iterations), 4-stage pipeline.
// smem: U 4x16K | vf 4x8K | ef 8K = 104K (2 CTAs/SM)
// 128B-row layout, swizzle (c16 ^ (r&7)) — conflict-free per ldmatrix phase.
// ===========================================================================
#define PV_NST      4
#define PVF_S_OFF   0
#define PVF_V_OFF   65536
#define PVF_EF_OFF  98304
#define PVF_SMEM    106496

__global__ __launch_bounds__(256, 2) void pv_fuse(
    const unsigned short* __restrict__ U, const float2* __restrict__ pt,
    const __half* __restrict__ vf,
    float* __restrict__ attn, float* __restrict__ Out)
{
    extern __shared__ char smx[];
    uint32_t sbase = smem_u32(smx);
    float* efb = (float*)(smx + PVF_EF_OFF);

    int g = blockIdx.z;
    int rowBase = blockIdx.x * 128;
    const char* uG  = (const char*)(U + (size_t)g * ATTN_PER_G);
    const char* vfG = (const char*)(vf + (size_t)g * (DK * TSEQ));
    float* Sg = attn + (size_t)g * ATTN_PER_G;

    int tid = threadIdx.x, lane = tid & 31, wid = tid >> 5;
    int wm = wid >> 1, wn = wid & 1;

    // issue one 64-col chunk (U 16KB + V 8KB) into stage s
    auto issue = [&](int c, int s) {
        uint32_t stS = sbase + PVF_S_OFF + s * 16384;
        #pragma unroll
        for (int p = 0; p < 4; p++) {
            int id = tid + p * 256;
            int r = id >> 3, c16 = id & 7;
            uint32_t dst = stS + r * 128 + (((uint32_t)c16 ^ (r & 7)) << 4);
            cpa16(dst, uG + (size_t)(rowBase + r) * 4096 + (size_t)c * 128 + c16 * 16);
        }
        uint32_t stV = sbase + PVF_V_OFF + s * 8192;
        #pragma unroll
        for (int p = 0; p < 2; p++) {
            int id = tid + p * 256;
            int r = id >> 3, c16 = id & 7;
            uint32_t dst = stV + r * 128 + (((uint32_t)c16 ^ (r & 7)) << 4);
            cpa16(dst, vfG + (size_t)r * 4096 + (size_t)c * 128 + c16 * 16);
        }
        CP_COMMIT();
    };

    issue(0, 0);
    issue(1, 1);
    issue(2, 2);

    // stats from partials -> ef
    if (tid < 128) {
        const float2* pp = pt + (size_t)g * 16 * TSEQ + rowBase + tid;
        float m = -3.4e38f, s = 0.0f;
        #pragma unroll
        for (int t = 0; t < 16; t++) {
            float2 q = pp[(size_t)t * TSEQ];
            efb[t * 128 + tid] = q.x;
            float mn = fmaxf(m, q.x);
            s = s * __expf(m - mn) + q.y * __expf(q.x - mn);
            m = mn;
        }
        float inv = 1.0f / s;
        #pragma unroll
        for (int t = 0; t < 16; t++)
            efb[t * 128 + tid] = __expf(efb[t * 128 + tid] - m) * inv;
    }
    __syncthreads();

    float oacc[2][4][4], tacc[2][4][4];
    #pragma unroll
    for (int a = 0; a < 2; a++)
        #pragma unroll
        for (int b = 0; b < 4; b++)
            #pragma unroll
            for (int r = 0; r < 4; r++) oacc[a][b][r] = 0.0f;

    const int NC = TSEQ >> 6;   // 32 chunks of 64 cols
    int stage = 0;
    for (int c = 0; c < NC; c++) {
        if (c < NC - 3) CP_WAIT(2); else CP_WAIT(0);
        __syncthreads();
        if (c + 3 < NC) issue(c + 3, (stage + 3) % PV_NST);

        int tidx = c >> 1;   // 128-col stat tile index
        uint32_t stS = sbase + PVF_S_OFF + stage * 16384;
        uint32_t stV = sbase + PVF_V_OFF + stage * 8192;

        // P write: p = fp16(u) * ef   (128 rows x 64 cols / 256 threads)
        #pragma unroll
        for (int it = 0; it < 8; it++) {
            int id = tid + it * 256;
            int r  = id >> 4;
            int c8 = id & 15;
            uint32_t off = r * 128 + (((uint32_t)(c8 >> 1) ^ (r & 7)) << 4)
                         + (c8 & 1) * 8;
            uint2 up = *(uint2*)(smx + PVF_S_OFF + stage * 16384 + off);
            __half2 h01 = *reinterpret_cast<__half2*>(&up.x);
            __half2 h23 = *reinterpret_cast<__half2*>(&up.y);
            float2 f01 = __half22float2(h01);
            float2 f23 = __half22float2(h23);
            float ef = efb[tidx * 128 + r];
            float4 p;
            p.x = f01.x * ef; p.y = f01.y * ef;
            p.z = f23.x * ef; p.w = f23.y * ef;
            *(float4*)(Sg + (size_t)(rowBase + r) * TSEQ + c * 64 + c8 * 4) = p;
        }

        if ((c & 1) == 0) {
            #pragma unroll
            for (int a = 0; a < 2; a++)
                #pragma unroll
                for (int b = 0; b < 4; b++)
                    #pragma unroll
                    for (int r = 0; r < 4; r++) tacc[a][b][r] = 0.0f;
        }

        // MMA: tacc += U @ V (fp16 direct), k-dim 64 = 4 kk steps
        #pragma unroll
        for (int kk = 0; kk < 4; kk++) {
            uint32_t au[2][4];
            #pragma unroll
            for (int mt = 0; mt < 2; mt++) {
                int r = wm * 32 + mt * 16 + (lane & 15);
                uint32_t c16 = kk * 2 + (lane >> 4);
                uint32_t off = r * 128 + ((c16 ^ (uint32_t)(r & 7)) << 4);
                ldsm4(au[mt], stS + off);
            }
            uint32_t bv[2][4];
            #pragma unroll
            for (int np = 0; np < 2; np++) {
                int n = wn * 32 + np * 16 + ((lane >> 4) << 3) + (lane & 7);
                uint32_t c16 = kk * 2 + ((lane >> 3) & 1);
                uint32_t off = n * 128 + ((c16 ^ (uint32_t)(n & 7)) << 4);
                ldsm4(bv[np], stV + off);
            }
            #pragma unroll
            for (int mt = 0; mt < 2; mt++)
                #pragma unroll
                for (int nt = 0; nt < 4; nt++)
                    mma16816h(tacc[mt][nt], au[mt], &bv[nt >> 1][(nt & 1) * 2]);
        }

        // fold at stat-tile end: O += ef[row] * tacc
        if ((c & 1) == 1) {
            #pragma unroll
            for (int mt = 0; mt < 2; mt++)
                #pragma unroll
                for (int hf = 0; hf < 2; hf++) {
                    int row = wm * 32 + mt * 16 + hf * 8 + (lane >> 2);
                    float ef = efb[tidx * 128 + row];
                    #pragma unroll
                    for (int nt = 0; nt < 4; nt++) {
                        oacc[mt][nt][hf*2]   += ef * tacc[mt][nt][hf*2];
                        oacc[mt][nt][hf*2+1] += ef * tacc[mt][nt][hf*2+1];
                    }
                }
        }
        stage = (stage + 1) % PV_NST;
    }

    // scatter epilogue (validated)
    int b  = g >> 4;
    int gg = g & 15;
    float* ob = Out + (size_t)b * 2097152;
    int rr  = rowBase + wm * 32 + (lane >> 2);
    int en0 = wn * 32 + (lane & 3) * 2;
    #pragma unroll
    for (int mt = 0; mt < 2; mt++) {
        #pragma unroll
        for (int hf = 0; hf < 2; hf++) {
            int s   = rr + mt * 16 + hf * 8;
            int thi = s >> 10;
            int d   = s & 1023;
            #pragma unroll
            for (int nt = 0; nt < 4; nt++) {
                int e  = en0 + nt * 8;
                int t0 = gg * 128 + 2 * e + thi;
                int t1 = gg * 128 + 2 * (e + 1) + thi;
                ob[(size_t)t0 * 1024 + d] = oacc[mt][nt][hf * 2 + 0];
                ob[(size_t)t1 * 1024 + d] = oacc[mt][nt][hf * 2 + 1];
            }
        }
    }
}

// ===========================================================================
// kernel_launch
// ===========================================================================
extern "C" void kernel_launch(void* const* d_in, const int* in_sizes, int n_in,
                              void* d_out, int out_size)
{
    const float* x  = (const float*)d_in[0];
    const float* sc = (const float*)d_in[1];
    const float* wq = (const float*)d_in[2];
    const float* bq = (const float*)d_in[3];
    const float* wk = (const float*)d_in[4];
    const float* bk = (const float*)d_in[5];
    const float* wv = (const float*)d_in[6];
    const float* bv = (const float*)d_in[7];

    float* out  = (float*)d_out;
    float* attn = out + OUT_ELEMS;

    float *q, *k, *v;
    float2* pt;
    unsigned short* u;
    __half* vf;
    __nv_bfloat16 *xh, *xl, *qh, *ql, *kh, *kl, *wh, *wl;
    cudaGetSymbolAddress((void**)&q,  g_q);
    cudaGetSymbolAddress((void**)&k,  g_k);
    cudaGetSymbolAddress((void**)&v,  g_v);
    cudaGetSymbolAddress((void**)&xh, g_xh);
    cudaGetSymbolAddress((void**)&xl, g_xl);
    cudaGetSymbolAddress((void**)&qh, g_qh);
    cudaGetSymbolAddress((void**)&ql, g_ql);
    cudaGetSymbolAddress((void**)&kh, g_kh);
    cudaGetSymbolAddress((void**)&kl, g_kl);
    cudaGetSymbolAddress((void**)&wh, g_wh);
    cudaGetSymbolAddress((void**)&wl, g_wl);
    cudaGetSymbolAddress((void**)&vf, g_vf);
    cudaGetSymbolAddress((void**)&pt, g_pt);
    cudaGetSymbolAddress((void**)&u,  g_u);

    cudaFuncSetAttribute(gemm_bb, cudaFuncAttributeMaxDynamicSharedMemorySize, GB_SMEM);
    cudaFuncSetAttribute(pv_fuse, cudaFuncAttributeMaxDynamicSharedMemorySize, PVF_SMEM);

    // 1) normalize x + split weights (fused launch)
    prep_kernel<<<4096 + 3072, 256>>>(x, sc, xh, xl, wq, wk, wv, wh, wl);

    // 2) projections (batched)
    gemm_bb<<<dim3(8, 32, 3), 256, GB_SMEM>>>(
        0, xh, xl, wh, wl, bq, bk, bv, q, k, v,
        DMODEL, DMODEL, DMODEL, DMODEL, 1.0f, nullptr, nullptr);

    // 3) scale_norm q/k/v
    scalenorm_qkv<<<dim3(ROWS, 3), 256>>>(q, k, v, sc, qh, ql, kh, kl);

    // 3b) V^T fp16
    vt_convert<<<dim3(TSEQ / 64, 1, NGRP), 256>>>(v, vf);

    // 4) QK: u = fp16 exp-domain S + per-tile softmax partials
    gemm_bb<<<dim3(16, 16, NGRP), 256, GB_SMEM>>>(
        1, qh, ql, kh, kl, nullptr, nullptr, nullptr, nullptr, nullptr, nullptr,
        DK, DK, TSEQ, DK, 0.125f, pt, u);

    // 5+6) fused softmax + P write + O = P @ V (fp16 MMA, 64-col chunks)
    pv_fuse<<<dim3(TSEQ / 128, 1, NGRP), 256, PVF_SMEM>>>(u, pt, vf, attn, out);
}